// round 15
// baseline (speedup 1.0000x reference)
#include <cuda_runtime.h>
#include <cuda_bf16.h>
#include <cstdint>
#include <math.h>

#define Bn 4096
#define INn 1024
#define Hn 1024
#define Fn 128
#define H4n 4096
#define EPS 1e-5f

// Scratch (static __device__ — no allocations allowed)
__device__ float g_scale[Bn * 256];   // [B][2F]
__device__ float g_U[Bn * 256];       // u fp32 (scale applied)
__device__ float g_Z[Bn * 256];       // Z = U·M^T per path
__device__ float g_M[2 * Fn * Fn];
__device__ float g_cm[2 * Fn];
__device__ float g_cpre[Bn * Hn];
__device__ float g_oact[Bn * Hn];
__device__ __nv_bfloat16 g_Uh[Bn * 256];    // gemm1 writes UNscaled; k_stats2 folds rstd in-place
__device__ __nv_bfloat16 g_Ul[Bn * 256];
__device__ __nv_bfloat16 g_Mh[2 * Fn * Fn];
__device__ __nv_bfloat16 g_Ml[2 * Fn * Fn];
__device__ __nv_bfloat16 g_Wh[H4n * 256];
__device__ __nv_bfloat16 g_Wl[H4n * 256];
__device__ __nv_bfloat16 g_Xh[2 * Bn * INn];
__device__ __nv_bfloat16 g_Xl[2 * Bn * INn];
__device__ __nv_bfloat16 g_Vh[2 * Fn * INn];
__device__ __nv_bfloat16 g_Vl[2 * Fn * INn];
__device__ float4 g_stats4[Bn];             // {rsi, rsh, mui*rsi, muh*rsh}
__device__ float g_bcomb[H4n];

// ============================ PTX helpers ===================================
__device__ __forceinline__ uint32_t smem_u32(const void* p) {
    uint32_t a;
    asm("{ .reg .u64 t; cvta.to.shared.u64 t, %1; cvt.u32.u64 %0, t; }" : "=r"(a) : "l"(p));
    return a;
}
__device__ __forceinline__ void cp_async16(uint32_t dst, const void* src) {
    asm volatile("cp.async.cg.shared.global [%0], [%1], 16;" :: "r"(dst), "l"(src) : "memory");
}
__device__ __forceinline__ void cp_commit() {
    asm volatile("cp.async.commit_group;" ::: "memory");
}
__device__ __forceinline__ void ldsm4(uint32_t* r, uint32_t a) {
    asm volatile("ldmatrix.sync.aligned.m8n8.x4.shared.b16 {%0,%1,%2,%3}, [%4];"
        : "=r"(r[0]), "=r"(r[1]), "=r"(r[2]), "=r"(r[3]) : "r"(a));
}
__device__ __forceinline__ void mma16816(float* d, const uint32_t* a, uint32_t b0, uint32_t b1) {
    asm volatile(
        "mma.sync.aligned.m16n8k16.row.col.f32.bf16.bf16.f32 "
        "{%0,%1,%2,%3}, {%4,%5,%6,%7}, {%8,%9}, {%0,%1,%2,%3};"
        : "+f"(d[0]), "+f"(d[1]), "+f"(d[2]), "+f"(d[3])
        : "r"(a[0]), "r"(a[1]), "r"(a[2]), "r"(a[3]), "r"(b0), "r"(b1));
}
__device__ __forceinline__ uint2 split_pack4(float4 d, uint2& lo) {
    __nv_bfloat16 h0 = __float2bfloat16(d.x), h1 = __float2bfloat16(d.y);
    __nv_bfloat16 h2 = __float2bfloat16(d.z), h3 = __float2bfloat16(d.w);
    __nv_bfloat16 l0 = __float2bfloat16(d.x - __bfloat162float(h0));
    __nv_bfloat16 l1 = __float2bfloat16(d.y - __bfloat162float(h1));
    __nv_bfloat16 l2 = __float2bfloat16(d.z - __bfloat162float(h2));
    __nv_bfloat16 l3 = __float2bfloat16(d.w - __bfloat162float(h3));
    uint2 hi;
    hi.x = (uint32_t)__bfloat16_as_ushort(h0) | ((uint32_t)__bfloat16_as_ushort(h1) << 16);
    hi.y = (uint32_t)__bfloat16_as_ushort(h2) | ((uint32_t)__bfloat16_as_ushort(h3) << 16);
    lo.x = (uint32_t)__bfloat16_as_ushort(l0) | ((uint32_t)__bfloat16_as_ushort(l1) << 16);
    lo.y = (uint32_t)__bfloat16_as_ushort(l2) | ((uint32_t)__bfloat16_as_ushort(l3) << 16);
    return hi;
}

// ===========================================================================
// Merged prep (verbatim from passing kernel)
// ===========================================================================
#define PB_ZERO   128
#define PB_SCALES (PB_ZERO + 4096)
#define PB_PREPX  (PB_SCALES + 8192)
#define PB_PREPWC (PB_PREPX + 256)
#define PB_PREPW  (PB_PREPWC + 4096)

__global__ __launch_bounds__(256) void k_prep(
    const float* __restrict__ topic,
    const float* __restrict__ thiw, const float* __restrict__ thib,
    const float* __restrict__ thhw, const float* __restrict__ thhb,
    const float* __restrict__ wib, const float* __restrict__ whb,
    const float* __restrict__ xin, const float* __restrict__ hx,
    const float* __restrict__ wic, const float* __restrict__ whc,
    const float* __restrict__ wia, const float* __restrict__ wha,
    const float* __restrict__ liw, const float* __restrict__ lhw,
    const float* __restrict__ lib, const float* __restrict__ lhb) {
    int blk = blockIdx.x, t = threadIdx.x;
    if (blk < PB_ZERO) {
        int i = blk * 256 + t;
        if (i < 2 * Fn * Fn) g_M[i] = 0.f;
        if (i < 2 * Fn) g_cm[i] = 0.f;
    } else if (blk < PB_SCALES) {
        int b = blk - PB_ZERO;
        int c = t;
        int path = c >> 7, f = c & 127;
        const float* thw = path ? thhw : thiw;
        const float* thb = path ? thhb : thib;
        const float* wb  = path ? whb  : wib;
        float t0 = topic[b * 3 + 0], t1 = topic[b * 3 + 1], t2 = topic[b * 3 + 2];
        float s = 0.f;
#pragma unroll
        for (int tt = 0; tt < 3; tt++) {
            float th = thb[tt] + t0 * thw[tt * 3 + 0] + t1 * thw[tt * 3 + 1] + t2 * thw[tt * 3 + 2];
            s += th * wb[f * 3 + tt];
        }
        g_scale[b * 256 + c] = s;
    } else if (blk < PB_PREPX) {
        int v = blk - PB_SCALES;
        int p = v >> 12, bb = v & 4095;
        const float* src = p ? hx : xin;
        int base = bb * 1024 + t * 4;
        float4 d = *(const float4*)(src + base);
        uint2 lo, hi = split_pack4(d, lo);
        *(uint2*)(g_Xh + p * (Bn * INn) + base) = hi;
        *(uint2*)(g_Xl + p * (Bn * INn) + base) = lo;
    } else if (blk < PB_PREPWC) {
        int v = blk - PB_PREPX;
        int p = v >> 7, bb = v & 127;
        const float* src = p ? whc : wic;
        int base = bb * 1024 + t * 4;
        float4 d = *(const float4*)(src + base);
        uint2 lo, hi = split_pack4(d, lo);
        *(uint2*)(g_Vh + p * (Fn * INn) + base) = hi;
        *(uint2*)(g_Vl + p * (Fn * INn) + base) = lo;
    } else {
        int C = blk - PB_PREPWC;
        int k = t;
        int h = ((C >> 5) << 3) + (C & 7);
        int gate = (C >> 3) & 3;
        int j = gate * 1024 + h;
        float v;
        if (k < 128) v = wia[j * 128 + k] * liw[j];
        else         v = wha[j * 128 + (k - 128)] * lhw[j];
        float hi = __bfloat162float(__float2bfloat16(v));
        g_Wh[C * 256 + k] = __float2bfloat16(v);
        g_Wl[C * 256 + k] = __float2bfloat16(v - hi);
        if (k == 0) g_bcomb[j] = lib[j] + lhb[j];
    }
}

// ---------------------------------------------------------------------------
__global__ __launch_bounds__(256) void k_syrk(const float* __restrict__ wia,
                                              const float* __restrict__ wha) {
    int p = blockIdx.y;
    const float* A = p ? wha : wia;
    __shared__ float sA[64 * 128];
    int tid = threadIdx.x;
    int f1 = (tid >> 4) * 8, f2 = (tid & 15) * 8;
    float acc[8][8];
#pragma unroll
    for (int i = 0; i < 8; i++)
#pragma unroll
        for (int k = 0; k < 8; k++) acc[i][k] = 0.f;
    float cs = 0.f;
    for (int jc = 0; jc < 2; jc++) {
        int j0 = blockIdx.x * 128 + jc * 64;
        for (int v = tid; v < 64 * 128 / 4; v += 256)
            ((float4*)sA)[v] = ((const float4*)(A + j0 * 128))[v];
        __syncthreads();
        for (int j = 0; j < 64; j++) {
            float l[8], r[8];
#pragma unroll
            for (int i = 0; i < 8; i++) { l[i] = sA[j * 128 + f1 + i]; r[i] = sA[j * 128 + f2 + i]; }
#pragma unroll
            for (int i = 0; i < 8; i++)
#pragma unroll
                for (int k = 0; k < 8; k++) acc[i][k] += l[i] * r[k];
        }
        if (tid < 128) {
            for (int j = 0; j < 64; j++) cs += sA[j * 128 + tid];
        }
        __syncthreads();
    }
#pragma unroll
    for (int i = 0; i < 8; i++)
#pragma unroll
        for (int k = 0; k < 8; k++)
            atomicAdd(&g_M[p * Fn * Fn + (f1 + i) * Fn + (f2 + k)], acc[i][k]);
    if (tid < 128) atomicAdd(&g_cm[p * Fn + tid], cs);
}

// ===========================================================================
// GEMM1 (R11-validated 64x128 config) + fused prepM blocks (rb >= 64).
// CTA 64(M) x 128(N). K=1024 in 16 chunks of 64. 8 warps 2(M)x4(N).
// Stage: Ah 8K, Al 8K, Bh 16K, Bl 16K = 48KB; 2 stages.
// ===========================================================================
#define G1_STAGE 49152
#define G1_SMEM  (2 * G1_STAGE)
#define GS_STAGE 49152
#define GS_SMEM  (2 * GS_STAGE)

__global__ __launch_bounds__(256, 2) void k_gemm1_mma() {
    // prepM side-blocks: rb in [64, 80) — split post-syrk M into bf16 hi/lo.
    if (blockIdx.x >= 64) {
        int idx = (blockIdx.x - 64) + blockIdx.y * 16;   // 0..31
        int base = idx * 1024 + threadIdx.x * 4;
        float4 d = *(const float4*)(g_M + base);
        uint2 lo, hi = split_pack4(d, lo);
        *(uint2*)(g_Mh + base) = hi;
        *(uint2*)(g_Ml + base) = lo;
        return;
    }
    extern __shared__ char smem[];
    uint32_t sb = smem_u32(smem);
    const int tid = threadIdx.x, l = tid & 31, wid = tid >> 5;
    const int wm = wid & 1, wn = wid >> 1;
    const int rb = blockIdx.x, p = blockIdx.y;
    const __nv_bfloat16* Xh = g_Xh + p * (Bn * INn);
    const __nv_bfloat16* Xl = g_Xl + p * (Bn * INn);
    const __nv_bfloat16* Vh = g_Vh + p * (Fn * INn);
    const __nv_bfloat16* Vl = g_Vl + p * (Fn * INn);

    float acc[2][4][4];
#pragma unroll
    for (int a = 0; a < 2; a++)
#pragma unroll
        for (int b = 0; b < 4; b++)
#pragma unroll
            for (int c = 0; c < 4; c++) acc[a][b][c] = 0.f;

#pragma unroll 1
    for (int cc = -1; cc < 16; cc++) {
        int ci = cc + 1;
        if (ci < 16) {
            uint32_t stage = sb + (uint32_t)(ci & 1) * G1_STAGE;
#pragma unroll
            for (int it = 0; it < 2; it++) {
                int v = tid + it * 256;
                int row = v >> 3, ch = v & 7;
                uint32_t soff = (uint32_t)((row * 8 + (ch ^ (row & 7))) << 4);
                cp_async16(stage + soff,        Xh + (rb * 64 + row) * 1024 + ci * 64 + ch * 8);
                cp_async16(stage + 8192 + soff, Xl + (rb * 64 + row) * 1024 + ci * 64 + ch * 8);
            }
#pragma unroll
            for (int it = 0; it < 4; it++) {
                int v = tid + it * 256;
                int row = v >> 3, ch = v & 7;
                uint32_t soff = (uint32_t)((row * 8 + (ch ^ (row & 7))) << 4);
                cp_async16(stage + 16384 + soff, Vh + row * 1024 + ci * 64 + ch * 8);
                cp_async16(stage + 32768 + soff, Vl + row * 1024 + ci * 64 + ch * 8);
            }
            cp_commit();
        }
        if (cc < 0) continue;
        if (cc < 15) asm volatile("cp.async.wait_group 1;" ::: "memory");
        else         asm volatile("cp.async.wait_group 0;" ::: "memory");
        __syncthreads();

        uint32_t Ah = sb + (uint32_t)(cc & 1) * G1_STAGE;
        uint32_t Al = Ah + 8192, Bh = Ah + 16384, Bl = Ah + 32768;
#pragma unroll
        for (int ks = 0; ks < 4; ks++) {
            uint32_t a[2][4], bh[2][4], bl[2][4];
#pragma unroll
            for (int mi = 0; mi < 2; mi++) {
                int r0 = wm * 32 + mi * 16 + ((l >> 3) & 1) * 8 + (l & 7);
                int ch = ks * 2 + (l >> 4);
                ldsm4(a[mi], Ah + (uint32_t)((r0 * 8 + (ch ^ (r0 & 7))) << 4));
            }
#pragma unroll
            for (int nfp = 0; nfp < 2; nfp++) {
                int m = l >> 3;
                int nr = wn * 32 + nfp * 16 + ((m >> 1) << 3) + (l & 7);
                int ch = ks * 2 + (m & 1);
                uint32_t soff = (uint32_t)((nr * 8 + (ch ^ (nr & 7))) << 4);
                ldsm4(bh[nfp], Bh + soff);
                ldsm4(bl[nfp], Bl + soff);
            }
#pragma unroll
            for (int mi = 0; mi < 2; mi++)
#pragma unroll
                for (int nf = 0; nf < 4; nf++) {
                    mma16816(acc[mi][nf], a[mi], bh[nf >> 1][(nf & 1) * 2], bh[nf >> 1][(nf & 1) * 2 + 1]);
                    mma16816(acc[mi][nf], a[mi], bl[nf >> 1][(nf & 1) * 2], bl[nf >> 1][(nf & 1) * 2 + 1]);
                }
#pragma unroll
            for (int mi = 0; mi < 2; mi++) {   // reload A as lo
                int r0 = wm * 32 + mi * 16 + ((l >> 3) & 1) * 8 + (l & 7);
                int ch = ks * 2 + (l >> 4);
                ldsm4(a[mi], Al + (uint32_t)((r0 * 8 + (ch ^ (r0 & 7))) << 4));
            }
#pragma unroll
            for (int mi = 0; mi < 2; mi++)
#pragma unroll
                for (int nf = 0; nf < 4; nf++)
                    mma16816(acc[mi][nf], a[mi], bh[nf >> 1][(nf & 1) * 2], bh[nf >> 1][(nf & 1) * 2 + 1]);
        }
        __syncthreads();
    }

    // epilogue: scale, write g_U fp32 + unscaled Uh/Ul
#pragma unroll
    for (int mi = 0; mi < 2; mi++)
#pragma unroll
        for (int rs = 0; rs < 2; rs++) {
            int row = rb * 64 + wm * 32 + mi * 16 + (l >> 2) + rs * 8;
#pragma unroll
            for (int nf = 0; nf < 4; nf++) {
                int fcol0 = wn * 32 + nf * 8 + (l & 3) * 2;
                int idx = row * 256 + p * 128 + fcol0;
                float u0 = acc[mi][nf][rs * 2 + 0] * g_scale[idx];
                float u1 = acc[mi][nf][rs * 2 + 1] * g_scale[idx + 1];
                *(float2*)(g_U + idx) = make_float2(u0, u1);
                __nv_bfloat16 h0 = __float2bfloat16(u0), h1 = __float2bfloat16(u1);
                __nv_bfloat16 l0 = __float2bfloat16(u0 - __bfloat162float(h0));
                __nv_bfloat16 l1 = __float2bfloat16(u1 - __bfloat162float(h1));
                *(uint32_t*)(g_Uh + idx) =
                    (uint32_t)__bfloat16_as_ushort(h0) | ((uint32_t)__bfloat16_as_ushort(h1) << 16);
                *(uint32_t*)(g_Ul + idx) =
                    (uint32_t)__bfloat16_as_ushort(l0) | ((uint32_t)__bfloat16_as_ushort(l1) << 16);
            }
        }
}

// ===========================================================================
// STATGEMM: Z[b,f] = sum_k U[b,k] M[k,f] per path
// ===========================================================================
__global__ __launch_bounds__(256, 2) void k_statgemm() {
    extern __shared__ char smem[];
    uint32_t sb = smem_u32(smem);
    const int tid = threadIdx.x, l = tid & 31, wid = tid >> 5;
    const int wm = wid & 1, wn = wid >> 1;
    const int rb = blockIdx.x, p = blockIdx.y;

    float acc[2][4][4];
#pragma unroll
    for (int a = 0; a < 2; a++)
#pragma unroll
        for (int b = 0; b < 4; b++)
#pragma unroll
            for (int c = 0; c < 4; c++) acc[a][b][c] = 0.f;

#pragma unroll 1
    for (int cc = -1; cc < 2; cc++) {
        int ci = cc + 1;
        if (ci < 2) {
            uint32_t stage = sb + (uint32_t)(ci & 1) * GS_STAGE;
#pragma unroll
            for (int it = 0; it < 2; it++) {
                int v = tid + it * 256;
                int row = v >> 3, ch = v & 7;
                uint32_t soff = (uint32_t)((row * 8 + (ch ^ (row & 7))) << 4);
                cp_async16(stage + soff,        g_Uh + (rb * 64 + row) * 256 + p * 128 + ci * 64 + ch * 8);
                cp_async16(stage + 8192 + soff, g_Ul + (rb * 64 + row) * 256 + p * 128 + ci * 64 + ch * 8);
            }
#pragma unroll
            for (int it = 0; it < 4; it++) {
                int v = tid + it * 256;
                int row = v >> 3, ch = v & 7;
                uint32_t soff = (uint32_t)((row * 8 + (ch ^ (row & 7))) << 4);
                cp_async16(stage + 16384 + soff, g_Mh + p * (Fn * Fn) + row * 128 + ci * 64 + ch * 8);
                cp_async16(stage + 32768 + soff, g_Ml + p * (Fn * Fn) + row * 128 + ci * 64 + ch * 8);
            }
            cp_commit();
        }
        if (cc < 0) continue;
        if (cc < 1) asm volatile("cp.async.wait_group 1;" ::: "memory");
        else        asm volatile("cp.async.wait_group 0;" ::: "memory");
        __syncthreads();

        uint32_t Ah = sb + (uint32_t)(cc & 1) * GS_STAGE;
        uint32_t Al = Ah + 8192, Bh = Ah + 16384, Bl = Ah + 32768;
#pragma unroll
        for (int ks = 0; ks < 4; ks++) {
            uint32_t a[2][4], bh[2][4], bl[2][4];
#pragma unroll
            for (int mi = 0; mi < 2; mi++) {
                int r0 = wm * 32 + mi * 16 + ((l >> 3) & 1) * 8 + (l & 7);
                int ch = ks * 2 + (l >> 4);
                ldsm4(a[mi], Ah + (uint32_t)((r0 * 8 + (ch ^ (r0 & 7))) << 4));
            }
#pragma unroll
            for (int nfp = 0; nfp < 2; nfp++) {
                int m = l >> 3;
                int nr = wn * 32 + nfp * 16 + ((m >> 1) << 3) + (l & 7);
                int ch = ks * 2 + (m & 1);
                uint32_t soff = (uint32_t)((nr * 8 + (ch ^ (nr & 7))) << 4);
                ldsm4(bh[nfp], Bh + soff);
                ldsm4(bl[nfp], Bl + soff);
            }
#pragma unroll
            for (int mi = 0; mi < 2; mi++)
#pragma unroll
                for (int nf = 0; nf < 4; nf++) {
                    mma16816(acc[mi][nf], a[mi], bh[nf >> 1][(nf & 1) * 2], bh[nf >> 1][(nf & 1) * 2 + 1]);
                    mma16816(acc[mi][nf], a[mi], bl[nf >> 1][(nf & 1) * 2], bl[nf >> 1][(nf & 1) * 2 + 1]);
                }
#pragma unroll
            for (int mi = 0; mi < 2; mi++) {
                int r0 = wm * 32 + mi * 16 + ((l >> 3) & 1) * 8 + (l & 7);
                int ch = ks * 2 + (l >> 4);
                ldsm4(a[mi], Al + (uint32_t)((r0 * 8 + (ch ^ (r0 & 7))) << 4));
            }
#pragma unroll
            for (int mi = 0; mi < 2; mi++)
#pragma unroll
                for (int nf = 0; nf < 4; nf++)
                    mma16816(acc[mi][nf], a[mi], bh[nf >> 1][(nf & 1) * 2], bh[nf >> 1][(nf & 1) * 2 + 1]);
        }
        __syncthreads();
    }

#pragma unroll
    for (int mi = 0; mi < 2; mi++)
#pragma unroll
        for (int rs = 0; rs < 2; rs++) {
            int row = rb * 64 + wm * 32 + mi * 16 + (l >> 2) + rs * 8;
#pragma unroll
            for (int nf = 0; nf < 4; nf++) {
                int fcol0 = wn * 32 + nf * 8 + (l & 3) * 2;
                int idx = row * 256 + p * 128 + fcol0;
                *(float2*)(g_Z + idx) =
                    make_float2(acc[mi][nf][rs * 2 + 0], acc[mi][nf][rs * 2 + 1]);
            }
        }
}

// ---------------------------------------------------------------------------
// Stats finalize + fused rstd fold into Uh/Ul.
__global__ __launch_bounds__(256) void k_stats2() {
    int t = threadIdx.x, lane = t & 31, w = t >> 5;
    int r = w >> 1, p = w & 1;
    int b0 = blockIdx.x * 4;
    int b = b0 + r;
    __shared__ float part[8][2];
    __shared__ float4 sst[4];
    float4 u  = ((const float4*)(g_U + b * 256 + p * 128))[lane];
    float4 z  = ((const float4*)(g_Z + b * 256 + p * 128))[lane];
    float4 cm = ((const float4*)(g_cm + p * 128))[lane];
    float q  = u.x * z.x + u.y * z.y + u.z * z.z + u.w * z.w;
    float dm = u.x * cm.x + u.y * cm.y + u.z * cm.z + u.w * cm.w;
#pragma unroll
    for (int o = 16; o; o >>= 1) {
        q  += __shfl_xor_sync(0xffffffffu, q, o);
        dm += __shfl_xor_sync(0xffffffffu, dm, o);
    }
    if (lane == 0) { part[w][0] = q; part[w][1] = dm; }
    __syncthreads();
    if (t < 4) {
        float qi = part[t * 2 + 0][0], di = part[t * 2 + 0][1];
        float qh = part[t * 2 + 1][0], dh = part[t * 2 + 1][1];
        float mui = di * (1.f / 4096.f), muh = dh * (1.f / 4096.f);
        float rsi = rsqrtf(qi * (1.f / 4096.f) - mui * mui + EPS);
        float rsh = rsqrtf(qh * (1.f / 4096.f) - muh * muh + EPS);
        float4 sv = make_float4(rsi, rsh, mui * rsi, muh * rsh);
        g_stats4[b0 + t] = sv;
        sst[t] = sv;
    }
    __syncthreads();
#pragma unroll
    for (int i = 0; i < 4; i++) {
        int idx = i * 256 + t;
        int rr = idx >> 8, col = idx & 255;
        float4 sv = sst[rr];
        float v = g_U[(b0 + rr) * 256 + col] * (col < 128 ? sv.x : sv.y);
        float hi = __bfloat162float(__float2bfloat16(v));
        g_Uh[(b0 + rr) * 256 + col] = __float2bfloat16(v);
        g_Ul[(b0 + rr) * 256 + col] = __float2bfloat16(v - hi);
    }
}

// ===========================================================================
// GEMM2 (validated mainloop + epilogue; a12 from g_stats4.zw)
// ===========================================================================
#define G2_STAGE 32768
#define G2_SMEM  (3 * G2_STAGE)

__global__ __launch_bounds__(256, 2) void k_gemm2_mma(
    const float* __restrict__ liw, const float* __restrict__ lhw,
    const float* __restrict__ cx) {
    extern __shared__ char smem[];
    uint32_t sb = smem_u32(smem);
    const int tid = threadIdx.x, l = tid & 31, wid = tid >> 5;
    const int wm = wid & 1, wn = wid >> 1;
    const int hb = blockIdx.x, rb = blockIdx.y;

    float acc[4][4][4];
#pragma unroll
    for (int a = 0; a < 4; a++)
#pragma unroll
        for (int b = 0; b < 4; b++)
#pragma unroll
            for (int c = 0; c < 4; c++) acc[a][b][c] = 0.f;

#pragma unroll 1
    for (int c = -2; c < 8; c++) {
        int ci = c + 2;
        if (ci < 8) {
            uint32_t stage = sb + (uint32_t)(ci % 3) * G2_STAGE;
#pragma unroll
            for (int it = 0; it < 2; it++) {
                int v = tid + it * 256;
                int row = v >> 2, ch = v & 3;
                uint32_t soff = (uint32_t)((row * 4 + (ch ^ ((row >> 1) & 3))) << 4);
                cp_async16(stage + soff,         g_Uh + (rb * 128 + row) * 256 + ci * 32 + ch * 8);
                cp_async16(stage + 8192 + soff,  g_Ul + (rb * 128 + row) * 256 + ci * 32 + ch * 8);
                cp_async16(stage + 16384 + soff, g_Wh + (hb * 128 + row) * 256 + ci * 32 + ch * 8);
                cp_async16(stage + 24576 + soff, g_Wl + (hb * 128 + row) * 256 + ci * 32 + ch * 8);
            }
            cp_commit();
        }
        if (c < 0) continue;
        if (c < 6)       asm volatile("cp.async.wait_group 2;" ::: "memory");
        else if (c == 6) asm volatile("cp.async.wait_group 1;" ::: "memory");
        else             asm volatile("cp.async.wait_group 0;" ::: "memory");
        __syncthreads();

        uint32_t Ah = sb + (uint32_t)(c % 3) * G2_STAGE;
        uint32_t Al = Ah + 8192, Bh = Ah + 16384, Bl = Ah + 24576;
#pragma unroll
        for (int ks = 0; ks < 2; ks++) {
            uint32_t a[4][4], bh[2][4], bl[2][4];
#pragma unroll
            for (int mi = 0; mi < 4; mi++) {
                int r0 = wm * 64 + mi * 16 + ((l >> 3) & 1) * 8 + (l & 7);
                int ch = ks * 2 + (l >> 4);
                ldsm4(a[mi], Ah + (uint32_t)((r0 * 4 + (ch ^ ((r0 >> 1) & 3))) << 4));
            }
#pragma unroll
            for (int nfp = 0; nfp < 2; nfp++) {
                int m = l >> 3;
                int nr = wn * 32 + nfp * 16 + ((m >> 1) << 3) + (l & 7);
                int ch = ks * 2 + (m & 1);
                uint32_t soff = (uint32_t)((nr * 4 + (ch ^ ((nr >> 1) & 3))) << 4);
                ldsm4(bh[nfp], Bh + soff);
                ldsm4(bl[nfp], Bl + soff);
            }
#pragma unroll
            for (int mi = 0; mi < 4; mi++)
#pragma unroll
                for (int nf = 0; nf < 4; nf++) {
                    mma16816(acc[mi][nf], a[mi], bh[nf >> 1][(nf & 1) * 2], bh[nf >> 1][(nf & 1) * 2 + 1]);
                    mma16816(acc[mi][nf], a[mi], bl[nf >> 1][(nf & 1) * 2], bl[nf >> 1][(nf & 1) * 2 + 1]);
                }
#pragma unroll
            for (int mi = 0; mi < 4; mi++) {
                int r0 = wm * 64 + mi * 16 + ((l >> 3) & 1) * 8 + (l & 7);
                int ch = ks * 2 + (l >> 4);
                ldsm4(a[mi], Al + (uint32_t)((r0 * 4 + (ch ^ ((r0 >> 1) & 3))) << 4));
            }
#pragma unroll
            for (int mi = 0; mi < 4; mi++)
#pragma unroll
                for (int nf = 0; nf < 4; nf++)
                    mma16816(acc[mi][nf], a[mi], bh[nf >> 1][(nf & 1) * 2], bh[nf >> 1][(nf & 1) * 2 + 1]);
        }
        __syncthreads();
    }

    const int q = l & 3;
    float cliw[4][2], clhw[4][2], cbc[4][2];
#pragma unroll
    for (int g = 0; g < 4; g++)
#pragma unroll
        for (int e = 0; e < 2; e++) {
            int h = (hb * 4 + wn) * 8 + q * 2 + e;
            int j = g * 1024 + h;
            cliw[g][e] = liw[j];
            clhw[g][e] = lhw[j];
            cbc[g][e]  = g_bcomb[j];
        }
#pragma unroll
    for (int mi = 0; mi < 4; mi++) {
#pragma unroll
        for (int rs = 0; rs < 2; rs++) {
            int row = rb * 128 + wm * 64 + mi * 16 + (l >> 2) + rs * 8;
            float4 st = g_stats4[row];
#pragma unroll
            for (int e = 0; e < 2; e++) {
                int h = (hb * 4 + wn) * 8 + q * 2 + e;
                float gv[4];
#pragma unroll
                for (int g = 0; g < 4; g++)
                    gv[g] = acc[mi][g][rs * 2 + e] + cbc[g][e]
                          - st.z * cliw[g][e] - st.w * clhw[g][e];
                float ig = 1.f / (1.f + __expf(-gv[0]));
                float fg = 1.f / (1.f + __expf(-gv[1]));
                float gg = tanhf(gv[2]);
                float og = 1.f / (1.f + __expf(-gv[3]));
                float cpre = fg * cx[row * Hn + h] + ig * gg;
                g_cpre[row * Hn + h] = cpre;
                g_oact[row * Hn + h] = og;
            }
        }
    }
}

// ---------------------------------------------------------------------------
// Final LN: warp-per-row, no block syncs, float4 I/O.
__global__ __launch_bounds__(256) void k_final(const float* __restrict__ lcw,
                                               const float* __restrict__ lcb,
                                               float* __restrict__ out) {
    int t = threadIdx.x, lane = t & 31, w = t >> 5;
    int b = blockIdx.x * 8 + w;
    const float4* cp4 = (const float4*)(g_cpre + b * Hn);
    const float4* oa4 = (const float4*)(g_oact + b * Hn);
    float4 c[8];
    float s = 0.f, s2 = 0.f;
#pragma unroll
    for (int i = 0; i < 8; i++) {
        c[i] = cp4[i * 32 + lane];
        s  += c[i].x + c[i].y + c[i].z + c[i].w;
        s2 += c[i].x * c[i].x + c[i].y * c[i].y + c[i].z * c[i].z + c[i].w * c[i].w;
    }
#pragma unroll
    for (int o = 16; o; o >>= 1) {
        s  += __shfl_xor_sync(0xffffffffu, s, o);
        s2 += __shfl_xor_sync(0xffffffffu, s2, o);
    }
    float mu = s * (1.f / 1024.f);
    float rstd = rsqrtf(s2 * (1.f / 1024.f) - mu * mu + EPS);
#pragma unroll
    for (int i = 0; i < 8; i++) {
        int h4 = i * 32 + lane;
        float4 wv = ((const float4*)lcw)[h4];
        float4 bv = ((const float4*)lcb)[h4];
        float4 ov = oa4[h4];
        float4 cy, hy;
        cy.x = (c[i].x - mu) * rstd * wv.x + bv.x;  hy.x = ov.x * tanhf(cy.x);
        cy.y = (c[i].y - mu) * rstd * wv.y + bv.y;  hy.y = ov.y * tanhf(cy.y);
        cy.z = (c[i].z - mu) * rstd * wv.z + bv.z;  hy.z = ov.z * tanhf(cy.z);
        cy.w = (c[i].w - mu) * rstd * wv.w + bv.w;  hy.w = ov.w * tanhf(cy.w);
        ((float4*)(out + Bn * Hn + b * Hn))[h4] = cy;
        ((float4*)(out + b * Hn))[h4] = hy;
    }
}

// ---------------------------------------------------------------------------
extern "C" void kernel_launch(void* const* d_in, const int* in_sizes, int n_in,
                              void* d_out, int out_size) {
    const float* input_ = (const float*)d_in[0];
    const float* hx     = (const float*)d_in[1];
    const float* cx     = (const float*)d_in[2];
    const float* topic  = (const float*)d_in[3];
    const float* wia    = (const float*)d_in[4];
    const float* wib    = (const float*)d_in[5];
    const float* wic    = (const float*)d_in[6];
    const float* wha    = (const float*)d_in[7];
    const float* whb    = (const float*)d_in[8];
    const float* whc    = (const float*)d_in[9];
    const float* thiw   = (const float*)d_in[10];
    const float* thib   = (const float*)d_in[11];
    const float* thhw   = (const float*)d_in[12];
    const float* thhb   = (const float*)d_in[13];
    const float* liw    = (const float*)d_in[14];
    const float* lib    = (const float*)d_in[15];
    const float* lhw    = (const float*)d_in[16];
    const float* lhb    = (const float*)d_in[17];
    const float* lcw    = (const float*)d_in[18];
    const float* lcb    = (const float*)d_in[19];
    float* out = (float*)d_out;

    cudaFuncSetAttribute(k_gemm1_mma, cudaFuncAttributeMaxDynamicSharedMemorySize, G1_SMEM);
    cudaFuncSetAttribute(k_statgemm, cudaFuncAttributeMaxDynamicSharedMemorySize, GS_SMEM);
    cudaFuncSetAttribute(k_gemm2_mma, cudaFuncAttributeMaxDynamicSharedMemorySize, G2_SMEM);

    k_prep<<<PB_PREPW, 256>>>(topic, thiw, thib, thhw, thhb, wib, whb,
                              input_, hx, wic, whc, wia, wha, liw, lhw, lib, lhb);
    k_syrk<<<dim3(32, 2), 256>>>(wia, wha);
    k_gemm1_mma<<<dim3(80, 2), 256, G1_SMEM>>>();   // rb<64: GEMM1; rb>=64: prepM
    k_statgemm<<<dim3(64, 2), 256, GS_SMEM>>>();
    k_stats2<<<1024, 256>>>();
    k_gemm2_mma<<<dim3(32, 32), 256, G2_SMEM>>>(liw, lhw, cx);
    k_final<<<512, 256>>>(lcw, lcb, out);
}